// round 16
// baseline (speedup 1.0000x reference)
#include <cuda_runtime.h>
#include <cuda_bf16.h>
#include <stdint.h>

// ---------------- problem constants ----------------
#define N_BINS    84
#define FFTLEN    2048
#define FREQ_BINS 1025
#define HOP       512
#define T_SAMPLES 8388608
#define N_FRAMES  16381
#define CHUNKS    64          // 64 chunks x 32 base-k = 2048
#define NTL       22          // ntiles: 176 cols = 88 re/im pairs >= 84 bins
#define NBPAD     96          // bins padded (16*6)
#define KQ        8           // split-K ways for W build
#define NCB       22          // colblks: 22 x 48 n covers [0,1055] >= [0,1024]

// ---------------- device globals ----------------
__device__ __nv_bfloat16 xh_b[T_SAMPLES];          // 16 MB
__device__ __nv_bfloat16 xl_b[T_SAMPLES];          // 16 MB
// B fragments, FUSED hi/lo: [chunk][k16(2)][nt(22)][lane(32)][bh0,bh1,bl0,bl1]
__device__ __align__(128) __nv_bfloat16 Bbig[CHUNKS * 2 * NTL * 32 * 8];
// split-K partials: [kq][n(2048)][bin(96)] (wr, wi)
__device__ float2 Wpart[KQ * FFTLEN * NBPAD];      // 12.6 MB

// ---------------- f32x2 helpers (prep) ----------------
__device__ __forceinline__ uint64_t pack2(float lo, float hi) {
    uint64_t r; asm("mov.b64 %0, {%1, %2};" : "=l"(r) : "f"(lo), "f"(hi)); return r;
}
__device__ __forceinline__ uint64_t dup2(float x) {
    uint64_t r; asm("mov.b64 %0, {%1, %1};" : "=l"(r) : "f"(x)); return r;
}
__device__ __forceinline__ void unpack2(uint64_t v, float& lo, float& hi) {
    asm("mov.b64 {%0, %1}, %2;" : "=f"(lo), "=f"(hi) : "l"(v));
}
__device__ __forceinline__ void ffma2(uint64_t& acc, uint64_t a, uint64_t b) {
    asm("fma.rn.f32x2 %0, %1, %2, %0;" : "+l"(acc) : "l"(a), "l"(b));
}

// =====================================================================
// Kernel 1: merged prep (verified R13).
// =====================================================================
#define WCTAS (NCB * KQ)      // 176

__global__ void __launch_bounds__(256) prep_all(
    const float* __restrict__ x,
    const float* __restrict__ kr, const float* __restrict__ ki,
    const float* __restrict__ wcos, const float* __restrict__ wsin)
{
    __shared__ float kct[32 * NBPAD * 2];   // [kl][b][{kr,ki}] 24 KB
    __shared__ float wct[32 * 48 * 2];      // [kl][nn][{c,s}]  12 KB
    const int tid = threadIdx.x;

    if (blockIdx.x >= WCTAS) {
        // ---------- x split ----------
        int i = ((blockIdx.x - WCTAS) * 256 + tid) * 8;
        float4 a = *reinterpret_cast<const float4*>(x + i);
        float4 c = *reinterpret_cast<const float4*>(x + i + 4);
        float v[8] = {a.x, a.y, a.z, a.w, c.x, c.y, c.z, c.w};
#pragma unroll
        for (int j = 0; j < 4; j++) {
            __nv_bfloat16 h0 = __float2bfloat16(v[2 * j]);
            __nv_bfloat16 h1 = __float2bfloat16(v[2 * j + 1]);
            __nv_bfloat16 l0 = __float2bfloat16(v[2 * j]     - __bfloat162float(h0));
            __nv_bfloat16 l1 = __float2bfloat16(v[2 * j + 1] - __bfloat162float(h1));
            *reinterpret_cast<__nv_bfloat162*>(xh_b + i + 2 * j) = __nv_bfloat162(h0, h1);
            *reinterpret_cast<__nv_bfloat162*>(xl_b + i + 2 * j) = __nv_bfloat162(l0, l1);
        }
        return;
    }

    // ---------- fused-W build (split-K, mirrored n, 3n x 6b) ----------
    const int n_t    = tid & 15;
    const int bin_g  = tid >> 4;                 // 0..15
    const int colblk = blockIdx.x % NCB;         // 0..21, 48 n each
    const int kq     = blockIdx.x / NCB;         // 0..7
    const int n0     = colblk * 48;
    const int t0     = kq * 4;
    const int t1     = (kq == KQ - 1) ? 33 : (t0 + 4);

    uint64_t accA[3][6], accB[3][6];
#pragma unroll
    for (int j = 0; j < 3; j++)
#pragma unroll
        for (int i = 0; i < 6; i++) { accA[j][i] = 0ull; accB[j][i] = 0ull; }

    for (int kt = t0; kt < t1; kt++) {
        const int k0 = kt * 32;
        __syncthreads();
        for (int i = tid; i < NBPAD * 32; i += 256) {
            int b = i >> 5, kl = i & 31, kg = k0 + kl;
            float vr = 0.f, vi = 0.f;
            if (b < N_BINS && kg < FREQ_BINS) {
                vr = kr[b * FREQ_BINS + kg];
                vi = ki[b * FREQ_BINS + kg];
            }
            kct[kl * (NBPAD * 2) + b * 2]     = vr;
            kct[kl * (NBPAD * 2) + b * 2 + 1] = vi;
        }
        for (int q = 0; q < 6; q++) {
            int i = tid + q * 256;               // 0..1535 = 32*48
            int kl = i / 48, nn = i % 48, kg = k0 + kl;
            float c = 0.f, s = 0.f;
            if (kg < FREQ_BINS) {
                c = wcos[kg * FFTLEN + n0 + nn];
                s = wsin[kg * FFTLEN + n0 + nn];
            }
            wct[kl * 96 + nn * 2]     = c;
            wct[kl * 96 + nn * 2 + 1] = s;
        }
        __syncthreads();
#pragma unroll 2
        for (int kl = 0; kl < 32; kl++) {
            const float* wp_ = &wct[kl * 96 + n_t * 2];
            uint64_t cs[3], sc[3];
#pragma unroll
            for (int j = 0; j < 3; j++) {
                float c = wp_[j * 32], s = wp_[j * 32 + 1];  // nn = n_t + 16j
                cs[j] = pack2(c, s);
                sc[j] = pack2(s, c);
            }
            const float* kp = &kct[kl * (NBPAD * 2) + bin_g * 2];
#pragma unroll
            for (int i = 0; i < 6; i++) {
                uint64_t ukr = dup2(kp[i * 32]);         // b = bin_g + 16i
                uint64_t uki = dup2(kp[i * 32 + 1]);
#pragma unroll
                for (int j = 0; j < 3; j++) {
                    ffma2(accA[j][i], ukr, cs[j]);
                    ffma2(accB[j][i], uki, sc[j]);
                }
            }
        }
    }
#pragma unroll
    for (int j = 0; j < 3; j++) {
        const int n = n0 + n_t + j * 16;
        float2* wpd = Wpart + (size_t)(kq * FFTLEN + n) * NBPAD;
        float2* wpm = Wpart + (size_t)(kq * FFTLEN + (FFTLEN - n)) * NBPAD;
#pragma unroll
        for (int i = 0; i < 6; i++) {
            int b = bin_g + 16 * i;
            if (b >= N_BINS) continue;
            float P, R, Q, S;
            unpack2(accA[j][i], P, R);
            unpack2(accB[j][i], Q, S);
            if (n <= 1024)           wpd[b] = make_float2(P - Q, R + S);
            if (n >= 1 && n <= 1023) wpm[b] = make_float2(P + Q, S - R);
        }
    }
}

// =====================================================================
// Kernel 2: combine split-K partials -> bf16 hi/lo -> Bbig (verified R13).
// =====================================================================
__device__ __forceinline__ uint32_t bpack(__nv_bfloat16 a, __nv_bfloat16 b) {
    __nv_bfloat162 t(a, b);                     // a -> low half
    return *reinterpret_cast<uint32_t*>(&t);
}

__global__ void __launch_bounds__(256) combine_k(void) {
    int idx = blockIdx.x * 256 + threadIdx.x;   // over 1024 * 96
    int np = idx / NBPAD, b = idx % NBPAD;
    if (b >= N_BINS) return;
    int n0 = np * 2;
    float wr0 = 0.f, wi0 = 0.f, wr1 = 0.f, wi1 = 0.f;
#pragma unroll
    for (int q = 0; q < KQ; q++) {
        float2 v0 = Wpart[(size_t)(q * FFTLEN + n0) * NBPAD + b];
        float2 v1 = Wpart[(size_t)(q * FFTLEN + n0 + 1) * NBPAD + b];
        wr0 += v0.x; wi0 += v0.y; wr1 += v1.x; wi1 += v1.y;
    }
    __nv_bfloat16 hr0 = __float2bfloat16(wr0);
    __nv_bfloat16 lr0 = __float2bfloat16(wr0 - __bfloat162float(hr0));
    __nv_bfloat16 hw0 = __float2bfloat16(wi0);
    __nv_bfloat16 lw0 = __float2bfloat16(wi0 - __bfloat162float(hw0));
    __nv_bfloat16 hr1 = __float2bfloat16(wr1);
    __nv_bfloat16 lr1 = __float2bfloat16(wr1 - __bfloat162float(hr1));
    __nv_bfloat16 hw1 = __float2bfloat16(wi1);
    __nv_bfloat16 lw1 = __float2bfloat16(wi1 - __bfloat162float(hw1));

    uint32_t* Bu = reinterpret_cast<uint32_t*>(Bbig);
    int chunk = n0 >> 5, k16 = (n0 >> 4) & 1, kc = (n0 & 15) >> 1;
    int reg = kc >> 2;
    int base = (chunk * 2 + k16) * NTL;
    {   // col = 2b (real part)
        int col = 2 * b;
        int lane = ((col & 7) << 2) | (kc & 3);
        int u32i = (base + (col >> 3)) * 128 + lane * 4 + reg;
        Bu[u32i]     = bpack(hr0, hr1);
        Bu[u32i + 2] = bpack(lr0, lr1);
    }
    {   // col = 2b+1 (imag part)
        int col = 2 * b + 1;
        int lane = ((col & 7) << 2) | (kc & 3);
        int u32i = (base + (col >> 3)) * 128 + lane * 4 + reg;
        Bu[u32i]     = bpack(hw0, hw1);
        Bu[u32i + 2] = bpack(lw0, lw1);
    }
}

// =====================================================================
// Main GEMM: CTA = 64 frames x 176 cols, 256 threads (8 warps = 2m x 4n),
// warp tile 32 x {48,48,40,40} (nt 6/6/5/5), full K per warp, 3-product bf16.
// A staged row-major (80B stride) via cp.async, read with ldmatrix.x4
// (verified R14); B frags one LDS.128 (verified R13).  2 CTAs/SM.
// =====================================================================
#define A_HALF_B 5120               // 64 rows * 80 B
#define A_ST_B   10240              // hi + lo
#define B_ST_B   22528              // 2*22*32*16
#define STAGE_B  32768
#define MM_SMEM  65536

__device__ __forceinline__ void mma16816(float* d, const uint32_t* a,
                                         const uint32_t* b) {
    asm volatile(
        "mma.sync.aligned.m16n8k16.row.col.f32.bf16.bf16.f32 "
        "{%0,%1,%2,%3}, {%4,%5,%6,%7}, {%8,%9}, {%0,%1,%2,%3};"
        : "+f"(d[0]), "+f"(d[1]), "+f"(d[2]), "+f"(d[3])
        : "r"(a[0]), "r"(a[1]), "r"(a[2]), "r"(a[3]), "r"(b[0]), "r"(b[1]));
}

__device__ __forceinline__ void issue_stage(int c, uint32_t smb, int f0, int tid) {
    uint32_t base = smb + (uint32_t)(c & 1) * STAGE_B;
    // A: 64 rows x 4 16B segs per half; 256 threads -> 1 (row,seg), both halves
    int row = tid >> 2;
    int j   = tid & 3;
    int g0 = (f0 + row) * HOP + c * 32;
    const char* srch = reinterpret_cast<const char*>(xh_b) + (size_t)g0 * 2;
    const char* srcl = reinterpret_cast<const char*>(xl_b) + (size_t)g0 * 2;
    unsigned sz = (g0 + j * 8 + 8 <= T_SAMPLES) ? 16u : 0u;
    uint32_t d = base + row * 80 + j * 16;
    asm volatile("cp.async.ca.shared.global [%0], [%1], 16, %2;"
                 :: "r"(d), "l"(srch + j * 16), "r"(sz));
    asm volatile("cp.async.ca.shared.global [%0], [%1], 16, %2;"
                 :: "r"(d + A_HALF_B), "l"(srcl + j * 16), "r"(sz));
    // B: 1408 16B segments
    const char* bs = reinterpret_cast<const char*>(Bbig) + (size_t)c * B_ST_B;
    uint32_t bd = base + A_ST_B;
#pragma unroll
    for (int i = 0; i < 6; i++) {
        int e = tid + i * 256;
        if (e < 1408)
            asm volatile("cp.async.ca.shared.global [%0], [%1], 16;"
                         :: "r"(bd + e * 16), "l"(bs + e * 16));
    }
    asm volatile("cp.async.commit_group;" ::: "memory");
}

__global__ void __launch_bounds__(256, 2) cqt_mma(float* __restrict__ out) {
    extern __shared__ uint32_t sm[];
    uint32_t smb;
    asm("{ .reg .u64 t; cvta.to.shared.u64 t, %1; cvt.u32.u64 %0, t; }"
        : "=r"(smb) : "l"((void*)sm));
    const int tid  = threadIdx.x;
    const int lane = tid & 31, wid = tid >> 5;
    const int wm   = wid & 1,  wn  = wid >> 1;       // wn 0..3
    const int ntg0 = wn * 6 - ((wn >= 3) ? 1 : 0);   // 0,6,12,17
    const int ntc  = (wn < 2) ? 6 : 5;
    const int f0   = blockIdx.x * 64;

    float acc[2][6][4];
#pragma unroll
    for (int a = 0; a < 2; a++)
#pragma unroll
        for (int b = 0; b < 6; b++)
#pragma unroll
            for (int d = 0; d < 4; d++) acc[a][b][d] = 0.f;

    issue_stage(0, smb, f0, tid);

    // ldmatrix per-lane addressing (verified R14)
    const int r_lm  = (lane & 7) + ((lane >> 3) & 1) * 8;
    const int kb_lm = (lane >> 4) * 16;

    for (int c = 0; c < CHUNKS; c++) {
        asm volatile("cp.async.wait_group 0;" ::: "memory");
        __syncthreads();
        if (c < CHUNKS - 1) issue_stage(c + 1, smb, f0, tid);

        const uint32_t abase = smb + (uint32_t)(c & 1) * STAGE_B;
        const uint32_t* B = sm + ((c & 1) * STAGE_B + A_ST_B) / 4;

#pragma unroll
        for (int k16 = 0; k16 < 2; k16++) {
            uint32_t ah[2][4], al[2][4];
            uint32_t ad0 = abase +
                (uint32_t)((wm * 32 + r_lm) * 80 + k16 * 32 + kb_lm);
#pragma unroll
            for (int mt = 0; mt < 2; mt++) {
                uint32_t ad = ad0 + mt * (16 * 80);
                asm volatile(
                    "ldmatrix.sync.aligned.m8n8.x4.shared.b16 {%0,%1,%2,%3}, [%4];"
                    : "=r"(ah[mt][0]), "=r"(ah[mt][1]),
                      "=r"(ah[mt][2]), "=r"(ah[mt][3]) : "r"(ad));
                asm volatile(
                    "ldmatrix.sync.aligned.m8n8.x4.shared.b16 {%0,%1,%2,%3}, [%4];"
                    : "=r"(al[mt][0]), "=r"(al[mt][1]),
                      "=r"(al[mt][2]), "=r"(al[mt][3]) : "r"(ad + A_HALF_B));
            }
#pragma unroll
            for (int j = 0; j < 6; j++) {
                if (j >= ntc) break;
                const uint4 q = *reinterpret_cast<const uint4*>(
                    B + (k16 * NTL + ntg0 + j) * 128 + lane * 4);
                uint32_t bh[2] = {q.x, q.y};
                uint32_t bl[2] = {q.z, q.w};
                mma16816(acc[0][j], ah[0], bh);
                mma16816(acc[1][j], ah[1], bh);
                mma16816(acc[0][j], al[0], bh);
                mma16816(acc[1][j], al[1], bh);
                mma16816(acc[0][j], ah[0], bl);
                mma16816(acc[1][j], ah[1], bl);
            }
        }
    }

    // ---- epilogue: magnitude + store ----
#pragma unroll
    for (int mt = 0; mt < 2; mt++) {
        int fr = f0 + wm * 32 + mt * 16 + (lane >> 2);
#pragma unroll
        for (int j = 0; j < 6; j++) {
            if (j >= ntc) break;
            int bin = (ntg0 + j) * 4 + (lane & 3);
            if (bin < N_BINS) {
                float* d = acc[mt][j];
                if (fr < N_FRAMES)
                    out[bin * N_FRAMES + fr] = sqrtf(d[0] * d[0] + d[1] * d[1]);
                if (fr + 8 < N_FRAMES)
                    out[bin * N_FRAMES + fr + 8] = sqrtf(d[2] * d[2] + d[3] * d[3]);
            }
        }
    }
}

// =====================================================================
extern "C" void kernel_launch(void* const* d_in, const int* in_sizes, int n_in,
                              void* d_out, int out_size)
{
    const float* x    = (const float*)d_in[0];
    const float* wcos = (const float*)d_in[1];
    const float* wsin = (const float*)d_in[2];
    const float* kr   = (const float*)d_in[3];
    const float* ki   = (const float*)d_in[4];
    float* out = (float*)d_out;

    prep_all<<<WCTAS + T_SAMPLES / 2048, 256>>>(x, kr, ki, wcos, wsin);
    combine_k<<<(1024 * NBPAD) / 256, 256>>>();

    cudaFuncSetAttribute(cqt_mma, cudaFuncAttributeMaxDynamicSharedMemorySize,
                         MM_SMEM);
    cqt_mma<<<16384 / 64, 256, MM_SMEM>>>(out);
}

// round 17
// speedup vs baseline: 1.0380x; 1.0380x over previous
#include <cuda_runtime.h>
#include <cuda_bf16.h>
#include <stdint.h>

// ---------------- problem constants ----------------
#define N_BINS    84
#define FFTLEN    2048
#define FREQ_BINS 1025
#define HOP       512
#define T_SAMPLES 8388608
#define N_FRAMES  16381
#define CHUNKS    64          // 64 chunks x 32 base-k = 2048
#define NTL       22          // ntiles: 176 cols = 88 re/im pairs >= 84 bins
#define NBPAD     96          // bins padded (16*6)
#define KQ        8           // split-K ways for W build
#define NCB       22          // colblks: 22 x 48 n covers [0,1055] >= [0,1024]
#define KROW      33          // kct row stride (odd -> conflict-free)

// ---------------- device globals ----------------
__device__ __nv_bfloat16 xh_b[T_SAMPLES];          // 16 MB
__device__ __nv_bfloat16 xl_b[T_SAMPLES];          // 16 MB
// B fragments, FUSED hi/lo: [chunk][k16(2)][nt(22)][lane(32)][bh0,bh1,bl0,bl1]
__device__ __align__(128) __nv_bfloat16 Bbig[CHUNKS * 2 * NTL * 32 * 8];
// split-K partials: [kq][n(2048)][bin(96)] (wr, wi)
__device__ float2 Wpart[KQ * FFTLEN * NBPAD];      // 12.6 MB

// ---------------- f32x2 helpers (prep) ----------------
__device__ __forceinline__ uint64_t pack2(float lo, float hi) {
    uint64_t r; asm("mov.b64 %0, {%1, %2};" : "=l"(r) : "f"(lo), "f"(hi)); return r;
}
__device__ __forceinline__ uint64_t dup2(float x) {
    uint64_t r; asm("mov.b64 %0, {%1, %1};" : "=l"(r) : "f"(x)); return r;
}
__device__ __forceinline__ void unpack2(uint64_t v, float& lo, float& hi) {
    asm("mov.b64 {%0, %1}, %2;" : "=f"(lo), "=f"(hi) : "l"(v));
}
__device__ __forceinline__ void ffma2(uint64_t& acc, uint64_t a, uint64_t b) {
    asm("fma.rn.f32x2 %0, %1, %2, %0;" : "+l"(acc) : "l"(a), "l"(b));
}

// =====================================================================
// Kernel 1: merged prep.  W-build kct now TRANSPOSED [b][kl] stride-33:
// coalesced LDG fill + conflict-free STS (was 32-way conflicted).
// =====================================================================
#define WCTAS (NCB * KQ)      // 176

__global__ void __launch_bounds__(256) prep_all(
    const float* __restrict__ x,
    const float* __restrict__ kr, const float* __restrict__ ki,
    const float* __restrict__ wcos, const float* __restrict__ wsin)
{
    __shared__ float kctr[NBPAD * KROW];    // [b][kl] 12.4 KB
    __shared__ float kcti[NBPAD * KROW];    // [b][kl] 12.4 KB
    __shared__ float wct[32 * 48 * 2];      // [kl][nn][{c,s}] 12 KB
    const int tid = threadIdx.x;

    if (blockIdx.x >= WCTAS) {
        // ---------- x split ----------
        int i = ((blockIdx.x - WCTAS) * 256 + tid) * 8;
        float4 a = *reinterpret_cast<const float4*>(x + i);
        float4 c = *reinterpret_cast<const float4*>(x + i + 4);
        float v[8] = {a.x, a.y, a.z, a.w, c.x, c.y, c.z, c.w};
#pragma unroll
        for (int j = 0; j < 4; j++) {
            __nv_bfloat16 h0 = __float2bfloat16(v[2 * j]);
            __nv_bfloat16 h1 = __float2bfloat16(v[2 * j + 1]);
            __nv_bfloat16 l0 = __float2bfloat16(v[2 * j]     - __bfloat162float(h0));
            __nv_bfloat16 l1 = __float2bfloat16(v[2 * j + 1] - __bfloat162float(h1));
            *reinterpret_cast<__nv_bfloat162*>(xh_b + i + 2 * j) = __nv_bfloat162(h0, h1);
            *reinterpret_cast<__nv_bfloat162*>(xl_b + i + 2 * j) = __nv_bfloat162(l0, l1);
        }
        return;
    }

    // ---------- fused-W build (split-K, mirrored n, 3n x 6b) ----------
    const int n_t    = tid & 15;
    const int bin_g  = tid >> 4;                 // 0..15
    const int colblk = blockIdx.x % NCB;         // 0..21, 48 n each
    const int kq     = blockIdx.x / NCB;         // 0..7
    const int n0     = colblk * 48;
    const int t0     = kq * 4;
    const int t1     = (kq == KQ - 1) ? 33 : (t0 + 4);

    uint64_t accA[3][6], accB[3][6];
#pragma unroll
    for (int j = 0; j < 3; j++)
#pragma unroll
        for (int i = 0; i < 6; i++) { accA[j][i] = 0ull; accB[j][i] = 0ull; }

    for (int kt = t0; kt < t1; kt++) {
        const int k0 = kt * 32;
        __syncthreads();
        // kct fill: coalesced LDG (kl fast) + conflict-free STS (stride 33)
        for (int i = tid; i < NBPAD * 32; i += 256) {
            int b = i >> 5, kl = i & 31, kg = k0 + kl;
            float vr = 0.f, vi = 0.f;
            if (b < N_BINS && kg < FREQ_BINS) {
                vr = kr[b * FREQ_BINS + kg];
                vi = ki[b * FREQ_BINS + kg];
            }
            kctr[b * KROW + kl] = vr;
            kcti[b * KROW + kl] = vi;
        }
        for (int q = 0; q < 6; q++) {
            int i = tid + q * 256;               // 0..1535 = 32*48
            int kl = i / 48, nn = i % 48, kg = k0 + kl;
            float c = 0.f, s = 0.f;
            if (kg < FREQ_BINS) {
                c = wcos[kg * FFTLEN + n0 + nn];
                s = wsin[kg * FFTLEN + n0 + nn];
            }
            wct[kl * 96 + nn * 2]     = c;
            wct[kl * 96 + nn * 2 + 1] = s;
        }
        __syncthreads();
#pragma unroll 2
        for (int kl = 0; kl < 32; kl++) {
            const float* wp_ = &wct[kl * 96 + n_t * 2];
            uint64_t cs[3], sc[3];
#pragma unroll
            for (int j = 0; j < 3; j++) {
                float c = wp_[j * 32], s = wp_[j * 32 + 1];  // nn = n_t + 16j
                cs[j] = pack2(c, s);
                sc[j] = pack2(s, c);
            }
            const float* pr = &kctr[bin_g * KROW + kl];
            const float* pi = &kcti[bin_g * KROW + kl];
#pragma unroll
            for (int i = 0; i < 6; i++) {
                uint64_t ukr = dup2(pr[i * (16 * KROW)]);   // b = bin_g + 16i
                uint64_t uki = dup2(pi[i * (16 * KROW)]);
#pragma unroll
                for (int j = 0; j < 3; j++) {
                    ffma2(accA[j][i], ukr, cs[j]);
                    ffma2(accB[j][i], uki, sc[j]);
                }
            }
        }
    }
#pragma unroll
    for (int j = 0; j < 3; j++) {
        const int n = n0 + n_t + j * 16;
        float2* wpd = Wpart + (size_t)(kq * FFTLEN + n) * NBPAD;
        float2* wpm = Wpart + (size_t)(kq * FFTLEN + (FFTLEN - n)) * NBPAD;
#pragma unroll
        for (int i = 0; i < 6; i++) {
            int b = bin_g + 16 * i;
            if (b >= N_BINS) continue;
            float P, R, Q, S;
            unpack2(accA[j][i], P, R);
            unpack2(accB[j][i], Q, S);
            if (n <= 1024)           wpd[b] = make_float2(P - Q, R + S);
            if (n >= 1 && n <= 1023) wpm[b] = make_float2(P + Q, S - R);
        }
    }
}

// =====================================================================
// Kernel 2: combine split-K partials -> bf16 hi/lo -> Bbig (verified R13).
// =====================================================================
__device__ __forceinline__ uint32_t bpack(__nv_bfloat16 a, __nv_bfloat16 b) {
    __nv_bfloat162 t(a, b);                     // a -> low half
    return *reinterpret_cast<uint32_t*>(&t);
}

__global__ void __launch_bounds__(256) combine_k(void) {
    int idx = blockIdx.x * 256 + threadIdx.x;   // over 1024 * 96
    int np = idx / NBPAD, b = idx % NBPAD;
    if (b >= N_BINS) return;
    int n0 = np * 2;
    float wr0 = 0.f, wi0 = 0.f, wr1 = 0.f, wi1 = 0.f;
#pragma unroll
    for (int q = 0; q < KQ; q++) {
        float2 v0 = Wpart[(size_t)(q * FFTLEN + n0) * NBPAD + b];
        float2 v1 = Wpart[(size_t)(q * FFTLEN + n0 + 1) * NBPAD + b];
        wr0 += v0.x; wi0 += v0.y; wr1 += v1.x; wi1 += v1.y;
    }
    __nv_bfloat16 hr0 = __float2bfloat16(wr0);
    __nv_bfloat16 lr0 = __float2bfloat16(wr0 - __bfloat162float(hr0));
    __nv_bfloat16 hw0 = __float2bfloat16(wi0);
    __nv_bfloat16 lw0 = __float2bfloat16(wi0 - __bfloat162float(hw0));
    __nv_bfloat16 hr1 = __float2bfloat16(wr1);
    __nv_bfloat16 lr1 = __float2bfloat16(wr1 - __bfloat162float(hr1));
    __nv_bfloat16 hw1 = __float2bfloat16(wi1);
    __nv_bfloat16 lw1 = __float2bfloat16(wi1 - __bfloat162float(hw1));

    uint32_t* Bu = reinterpret_cast<uint32_t*>(Bbig);
    int chunk = n0 >> 5, k16 = (n0 >> 4) & 1, kc = (n0 & 15) >> 1;
    int reg = kc >> 2;
    int base = (chunk * 2 + k16) * NTL;
    {   // col = 2b (real part)
        int col = 2 * b;
        int lane = ((col & 7) << 2) | (kc & 3);
        int u32i = (base + (col >> 3)) * 128 + lane * 4 + reg;
        Bu[u32i]     = bpack(hr0, hr1);
        Bu[u32i + 2] = bpack(lr0, lr1);
    }
    {   // col = 2b+1 (imag part)
        int col = 2 * b + 1;
        int lane = ((col & 7) << 2) | (kc & 3);
        int u32i = (base + (col >> 3)) * 128 + lane * 4 + reg;
        Bu[u32i]     = bpack(hw0, hw1);
        Bu[u32i + 2] = bpack(lw0, lw1);
    }
}

// =====================================================================
// Main GEMM (verified R15 best): CTA = 64 frames x 176 cols, 128 threads
// (4 warps = 2m x 2n), warp tile 32 x 88, full K per warp, 3-product bf16.
// A staged row-major (80B stride) via cp.async, ldmatrix.x4 reads;
// B frags one LDS.128.  3 CTAs/SM (64 KB smem each), grid 256.
// =====================================================================
#define A_HALF_B 5120               // 64 rows * 80 B
#define A_ST_B   10240              // hi + lo
#define B_ST_B   22528              // 2*22*32*16
#define STAGE_B  32768
#define MM_SMEM  65536

__device__ __forceinline__ void mma16816(float* d, const uint32_t* a,
                                         const uint32_t* b) {
    asm volatile(
        "mma.sync.aligned.m16n8k16.row.col.f32.bf16.bf16.f32 "
        "{%0,%1,%2,%3}, {%4,%5,%6,%7}, {%8,%9}, {%0,%1,%2,%3};"
        : "+f"(d[0]), "+f"(d[1]), "+f"(d[2]), "+f"(d[3])
        : "r"(a[0]), "r"(a[1]), "r"(a[2]), "r"(a[3]), "r"(b[0]), "r"(b[1]));
}

__device__ __forceinline__ void issue_stage(int c, uint32_t smb, int f0, int tid) {
    uint32_t base = smb + (uint32_t)(c & 1) * STAGE_B;
    // A: 64 rows x 64B per half; thread covers 2 of 4 segs for both halves
    int row = tid >> 1;
    int part = tid & 1;
    int g0 = (f0 + row) * HOP + c * 32;
    const char* srch = reinterpret_cast<const char*>(xh_b) + (size_t)g0 * 2;
    const char* srcl = reinterpret_cast<const char*>(xl_b) + (size_t)g0 * 2;
#pragma unroll
    for (int jj = 0; jj < 2; jj++) {
        int j = part * 2 + jj;
        unsigned sz = (g0 + j * 8 + 8 <= T_SAMPLES) ? 16u : 0u;
        uint32_t d = base + row * 80 + j * 16;
        asm volatile("cp.async.ca.shared.global [%0], [%1], 16, %2;"
                     :: "r"(d), "l"(srch + j * 16), "r"(sz));
        asm volatile("cp.async.ca.shared.global [%0], [%1], 16, %2;"
                     :: "r"(d + A_HALF_B), "l"(srcl + j * 16), "r"(sz));
    }
    // B: 1408 16B segments, 11 per thread
    const char* bs = reinterpret_cast<const char*>(Bbig) + (size_t)c * B_ST_B;
    uint32_t bd = base + A_ST_B;
#pragma unroll
    for (int i = 0; i < 11; i++) {
        int e = tid + i * 128;
        asm volatile("cp.async.ca.shared.global [%0], [%1], 16;"
                     :: "r"(bd + e * 16), "l"(bs + e * 16));
    }
    asm volatile("cp.async.commit_group;" ::: "memory");
}

__global__ void __launch_bounds__(128, 3) cqt_mma(float* __restrict__ out) {
    extern __shared__ uint32_t sm[];
    uint32_t smb;
    asm("{ .reg .u64 t; cvta.to.shared.u64 t, %1; cvt.u32.u64 %0, t; }"
        : "=r"(smb) : "l"((void*)sm));
    const int tid  = threadIdx.x;
    const int lane = tid & 31, wid = tid >> 5;
    const int wm   = wid & 1,  wn  = wid >> 1;
    const int f0   = blockIdx.x * 64;

    float acc[2][11][4];
#pragma unroll
    for (int a = 0; a < 2; a++)
#pragma unroll
        for (int b = 0; b < 11; b++)
#pragma unroll
            for (int d = 0; d < 4; d++) acc[a][b][d] = 0.f;

    issue_stage(0, smb, f0, tid);

    // ldmatrix per-lane addressing (verified R14)
    const int r_lm  = (lane & 7) + ((lane >> 3) & 1) * 8;
    const int kb_lm = (lane >> 4) * 16;

    for (int c = 0; c < CHUNKS; c++) {
        asm volatile("cp.async.wait_group 0;" ::: "memory");
        __syncthreads();
        if (c < CHUNKS - 1) issue_stage(c + 1, smb, f0, tid);

        const uint32_t abase = smb + (uint32_t)(c & 1) * STAGE_B;
        const uint32_t* B = sm + ((c & 1) * STAGE_B + A_ST_B) / 4;

#pragma unroll
        for (int k16 = 0; k16 < 2; k16++) {
            uint32_t ah[2][4], al[2][4];
            uint32_t ad0 = abase +
                (uint32_t)((wm * 32 + r_lm) * 80 + k16 * 32 + kb_lm);
#pragma unroll
            for (int mt = 0; mt < 2; mt++) {
                uint32_t ad = ad0 + mt * (16 * 80);
                asm volatile(
                    "ldmatrix.sync.aligned.m8n8.x4.shared.b16 {%0,%1,%2,%3}, [%4];"
                    : "=r"(ah[mt][0]), "=r"(ah[mt][1]),
                      "=r"(ah[mt][2]), "=r"(ah[mt][3]) : "r"(ad));
                asm volatile(
                    "ldmatrix.sync.aligned.m8n8.x4.shared.b16 {%0,%1,%2,%3}, [%4];"
                    : "=r"(al[mt][0]), "=r"(al[mt][1]),
                      "=r"(al[mt][2]), "=r"(al[mt][3]) : "r"(ad + A_HALF_B));
            }
#pragma unroll
            for (int nt = 0; nt < 11; nt++) {
                const uint4 q = *reinterpret_cast<const uint4*>(
                    B + (k16 * NTL + wn * 11 + nt) * 128 + lane * 4);
                uint32_t bh[2] = {q.x, q.y};
                uint32_t bl[2] = {q.z, q.w};
                mma16816(acc[0][nt], ah[0], bh);
                mma16816(acc[1][nt], ah[1], bh);
                mma16816(acc[0][nt], al[0], bh);
                mma16816(acc[1][nt], al[1], bh);
                mma16816(acc[0][nt], ah[0], bl);
                mma16816(acc[1][nt], ah[1], bl);
            }
        }
    }

    // ---- epilogue: magnitude + store ----
#pragma unroll
    for (int mt = 0; mt < 2; mt++) {
        int fr = f0 + wm * 32 + mt * 16 + (lane >> 2);
#pragma unroll
        for (int nt = 0; nt < 11; nt++) {
            int bin = wn * 44 + nt * 4 + (lane & 3);
            if (bin < N_BINS) {
                float* d = acc[mt][nt];
                if (fr < N_FRAMES)
                    out[bin * N_FRAMES + fr] = sqrtf(d[0] * d[0] + d[1] * d[1]);
                if (fr + 8 < N_FRAMES)
                    out[bin * N_FRAMES + fr + 8] = sqrtf(d[2] * d[2] + d[3] * d[3]);
            }
        }
    }
}

// =====================================================================
extern "C" void kernel_launch(void* const* d_in, const int* in_sizes, int n_in,
                              void* d_out, int out_size)
{
    const float* x    = (const float*)d_in[0];
    const float* wcos = (const float*)d_in[1];
    const float* wsin = (const float*)d_in[2];
    const float* kr   = (const float*)d_in[3];
    const float* ki   = (const float*)d_in[4];
    float* out = (float*)d_out;

    prep_all<<<WCTAS + T_SAMPLES / 2048, 256>>>(x, kr, ki, wcos, wsin);
    combine_k<<<(1024 * NBPAD) / 256, 256>>>();

    cudaFuncSetAttribute(cqt_mma, cudaFuncAttributeMaxDynamicSharedMemorySize,
                         MM_SMEM);
    cqt_mma<<<16384 / 64, 128, MM_SMEM>>>(out);
}